// round 1
// baseline (speedup 1.0000x reference)
#include <cuda_runtime.h>
#include <cstdint>

#define B_ 128
#define S_ 256
#define C_ 512
#define T_ 128
#define V_ 256
#define H_ 512
#define A_ 512
#define NG 2048   /* 4*H */
#define KX 1024   /* A + H */

// ---------------- device scratch (static; no allocations allowed) ----------
__device__ float g_keys [B_*S_*A_];   // 64 MB
__device__ float g_kproj[B_*S_*A_];   // 64 MB
__device__ float g_HcT  [H_*A_];      // Hc_w transposed: HcT[k][m] = Hc_w[m][k]
__device__ float g_Wcomb[A_*H_];      // Wq @ Hc_w  (qw = h @ Wcomb^T + bqc)
__device__ float g_bqc  [A_];
__device__ float g_Wcat [NG*KX];      // [W_ih[:,V:] | W_hh] rearranged, 8 MB
__device__ float g_bcomb[NG];
__device__ float g_h    [B_*H_];
__device__ float g_c    [B_*H_];
__device__ float g_X    [B_*KX];      // [ctx | h] per batch row
__device__ float g_qw   [B_*A_];
__device__ float g_gates[B_*NG];

// ---------------- helpers ---------------------------------------------------
__device__ __forceinline__ void ffma2(float2 &c, float2 a, float2 b) {
    asm("fma.rn.f32x2 %0, %1, %2, %0;"
        : "+l"(reinterpret_cast<unsigned long long&>(c))
        : "l"(reinterpret_cast<unsigned long long&>(a)),
          "l"(reinterpret_cast<unsigned long long&>(b)));
}

__device__ __forceinline__ float wsum(float v) {
    #pragma unroll
    for (int o = 16; o > 0; o >>= 1) v += __shfl_down_sync(0xffffffffu, v, o);
    return v;
}
__device__ __forceinline__ float wmax(float v) {
    #pragma unroll
    for (int o = 16; o > 0; o >>= 1) v = fmaxf(v, __shfl_down_sync(0xffffffffu, v, o));
    return v;
}
__device__ __forceinline__ float sigm(float x) { return 1.f / (1.f + expf(-x)); }

// ---------------- generic NT GEMM: C[M,N] (+)= A[M,K] * B[N,K]^T ------------
// BM=BN=64, BK=16, 256 threads, 4x4 micro-tile via packed f32x2 FMA.
// gridDim.z = split-K factor (kChunk = K/gridDim.z).
// ATOMIC=false: C = dot + bias[n] (overwrite). ATOMIC=true: atomicAdd into C.
template<bool ATOMIC>
__global__ void gemm_nt(const float* __restrict__ A, const float* __restrict__ Bm,
                        const float* __restrict__ bias, float* __restrict__ C,
                        int M, int N, int K, int ldc)
{
    __shared__ __align__(16) float As[16][68];
    __shared__ __align__(16) float Bs[16][68];
    const int tid = threadIdx.x;
    const int tx = tid & 15, ty = tid >> 4;
    const int n0 = blockIdx.x * 64, m0 = blockIdx.y * 64;
    const int kChunk = K / gridDim.z;
    const int k0 = blockIdx.z * kChunk;

    float2 acc[4][2];
    #pragma unroll
    for (int i = 0; i < 4; i++) { acc[i][0] = make_float2(0.f,0.f); acc[i][1] = make_float2(0.f,0.f); }

    const int lr = tid >> 2;          // 0..63 (tile row)
    const int lc = (tid & 3) * 4;     // 0,4,8,12 (k group)

    for (int kb = k0; kb < k0 + kChunk; kb += 16) {
        float4 av = *(const float4*)(A  + (size_t)(m0 + lr) * K + kb + lc);
        float4 bv = *(const float4*)(Bm + (size_t)(n0 + lr) * K + kb + lc);
        As[lc+0][lr] = av.x; As[lc+1][lr] = av.y; As[lc+2][lr] = av.z; As[lc+3][lr] = av.w;
        Bs[lc+0][lr] = bv.x; Bs[lc+1][lr] = bv.y; Bs[lc+2][lr] = bv.z; Bs[lc+3][lr] = bv.w;
        __syncthreads();
        #pragma unroll
        for (int kk = 0; kk < 16; kk++) {
            float4 a4 = *(const float4*)&As[kk][ty * 4];
            float4 b4 = *(const float4*)&Bs[kk][tx * 4];
            float2 b0 = make_float2(b4.x, b4.y), b1 = make_float2(b4.z, b4.w);
            float a_[4] = {a4.x, a4.y, a4.z, a4.w};
            #pragma unroll
            for (int i = 0; i < 4; i++) {
                float2 aa = make_float2(a_[i], a_[i]);
                ffma2(acc[i][0], aa, b0);
                ffma2(acc[i][1], aa, b1);
            }
        }
        __syncthreads();
    }

    #pragma unroll
    for (int i = 0; i < 4; i++) {
        int m = m0 + ty * 4 + i;
        float vals[4] = {acc[i][0].x, acc[i][0].y, acc[i][1].x, acc[i][1].y};
        #pragma unroll
        for (int j = 0; j < 4; j++) {
            int n = n0 + tx * 4 + j;
            if (ATOMIC) atomicAdd(&C[(size_t)m * ldc + n], vals[j]);
            else        C[(size_t)m * ldc + n] = vals[j] + (bias ? bias[n] : 0.f);
        }
    }
}

// ---------------- one-time prep kernels -------------------------------------
__global__ void k_transpose(const float* __restrict__ W, float* __restrict__ Wt,
                            int R, int Ccols) {
    int idx = blockIdx.x * 256 + threadIdx.x;
    if (idx < R * Ccols) {
        int r = idx / Ccols, c = idx % Ccols;
        Wt[(size_t)c * R + r] = W[idx];
    }
}

__global__ void k_bqc(const float* __restrict__ Wq, const float* __restrict__ bq,
                      const float* __restrict__ Hcb) {
    int a = threadIdx.x;
    float s = bq[a];
    for (int m = 0; m < A_; m++) s += Wq[a * A_ + m] * Hcb[m];
    g_bqc[a] = s;
}

__global__ void k_wcat(const float* __restrict__ W_ih, const float* __restrict__ W_hh,
                       const float* __restrict__ b_ih, const float* __restrict__ b_hh) {
    int idx = blockIdx.x * 256 + threadIdx.x;
    if (idx < NG * KX) {
        int n = idx >> 10, k = idx & 1023;
        g_Wcat[idx] = (k < A_) ? W_ih[n * (V_ + A_) + V_ + k] : W_hh[n * H_ + (k - A_)];
    }
    if (idx < NG) g_bcomb[idx] = b_ih[idx] + b_hh[idx];
}

__global__ void k_zero() {
    int idx = blockIdx.x * 256 + threadIdx.x;   // B*H threads
    g_h[idx] = 0.f; g_c[idx] = 0.f;
    int b = idx >> 9, j = idx & 511;
    g_X[b * KX + A_ + j] = 0.f;
}

// ---------------- per-step kernels -------------------------------------------
__global__ void k_step_init(int t, const int* __restrict__ labels,
                            const float* __restrict__ W_ih,
                            const float* __restrict__ bout,
                            float* __restrict__ out) {
    int b = blockIdx.x, tid = threadIdx.x;
    int lbl = labels[b * T_ + (t > 0 ? t - 1 : 0)];
    for (int a = tid; a < A_; a += 256) g_qw[b * A_ + a] = g_bqc[a];
    for (int n = tid; n < NG; n += 256)
        g_gates[b * NG + n] = g_bcomb[n] + W_ih[n * (V_ + A_) + lbl];
    for (int v = tid; v < V_; v += 256)
        out[((size_t)b * T_ + t) * V_ + v] = bout[v];
}

__global__ void k_attention(const float* __restrict__ va) {
    int b = blockIdx.x, tid = threadIdx.x;
    int lane = tid & 31, wp = tid >> 5;
    __shared__ __align__(16) float qws[A_];
    __shared__ __align__(16) float vs[A_];
    __shared__ float ss[S_];
    __shared__ float red[8];

    for (int a = tid; a < A_; a += 256) { qws[a] = g_qw[b * A_ + a]; vs[a] = va[a]; }
    __syncthreads();

    const float4* qw4 = (const float4*)qws;
    const float4* vs4 = (const float4*)vs;
    for (int r = 0; r < 32; r++) {
        int j = wp * 32 + r;
        const float4* kp4 = (const float4*)(g_kproj + ((size_t)b * S_ + j) * A_);
        float acc = 0.f;
        #pragma unroll
        for (int it = 0; it < 4; it++) {
            int idx = it * 32 + lane;
            float4 kv = kp4[idx];
            float4 qv = qw4[idx];
            float4 vv = vs4[idx];
            acc += vv.x * tanhf(kv.x + qv.x);
            acc += vv.y * tanhf(kv.y + qv.y);
            acc += vv.z * tanhf(kv.z + qv.z);
            acc += vv.w * tanhf(kv.w + qv.w);
        }
        acc = wsum(acc);
        if (lane == 0) ss[j] = acc;
    }
    __syncthreads();

    float v = ss[tid];
    float m = wmax(v);
    if (lane == 0) red[wp] = m;
    __syncthreads();
    m = red[0];
    #pragma unroll
    for (int i = 1; i < 8; i++) m = fmaxf(m, red[i]);
    float e = expf(v - m);
    float s = wsum(e);
    __syncthreads();
    if (lane == 0) red[wp] = s;
    __syncthreads();
    s = red[0];
    #pragma unroll
    for (int i = 1; i < 8; i++) s += red[i];
    ss[tid] = e / s;
    __syncthreads();

    #pragma unroll
    for (int rep = 0; rep < 2; rep++) {
        int a = tid + rep * 256;
        const float* kb = g_keys + (size_t)b * S_ * A_ + a;
        float acc = 0.f;
        #pragma unroll 4
        for (int j = 0; j < S_; j++) acc += ss[j] * kb[(size_t)j * A_];
        g_X[b * KX + a] = acc;
    }
}

__global__ void k_cell() {
    int idx = blockIdx.x * 256 + threadIdx.x;  // B*H
    int b = idx >> 9, j = idx & 511;
    const float* g = g_gates + (size_t)b * NG;
    float ig = g[j], fg = g[512 + j], gg = g[1024 + j], og = g[1536 + j];
    float c  = g_c[idx];
    float cn = sigm(fg) * c + sigm(ig) * tanhf(gg);
    float hn = sigm(og) * tanhf(cn);
    g_c[idx] = cn;
    g_h[idx] = hn;
    g_X[b * KX + A_ + j] = hn;
}

// ---------------- host driver -------------------------------------------------
extern "C" void kernel_launch(void* const* d_in, const int* in_sizes, int n_in,
                              void* d_out, int out_size) {
    (void)in_sizes; (void)n_in; (void)out_size;
    const float* feats = (const float*)d_in[0];
    const int*   labels= (const int*)  d_in[1];
    const float* Ic_w  = (const float*)d_in[2];
    const float* Ic_b  = (const float*)d_in[3];
    const float* Hc_w  = (const float*)d_in[4];
    const float* Hc_b  = (const float*)d_in[5];
    const float* Wq    = (const float*)d_in[6];
    const float* bq    = (const float*)d_in[7];
    const float* Wk    = (const float*)d_in[8];
    const float* bk    = (const float*)d_in[9];
    const float* va    = (const float*)d_in[10];
    const float* W_ih  = (const float*)d_in[11];
    const float* b_ih  = (const float*)d_in[12];
    const float* W_hh  = (const float*)d_in[13];
    const float* b_hh  = (const float*)d_in[14];
    const float* Wout  = (const float*)d_in[15];
    const float* bout  = (const float*)d_in[16];
    float* out = (float*)d_out;

    float *p_keys, *p_kproj, *p_HcT, *p_Wcomb, *p_Wcat, *p_h, *p_X, *p_qw, *p_gates;
    cudaGetSymbolAddress((void**)&p_keys,  g_keys);
    cudaGetSymbolAddress((void**)&p_kproj, g_kproj);
    cudaGetSymbolAddress((void**)&p_HcT,   g_HcT);
    cudaGetSymbolAddress((void**)&p_Wcomb, g_Wcomb);
    cudaGetSymbolAddress((void**)&p_Wcat,  g_Wcat);
    cudaGetSymbolAddress((void**)&p_h,     g_h);
    cudaGetSymbolAddress((void**)&p_X,     g_X);
    cudaGetSymbolAddress((void**)&p_qw,    g_qw);
    cudaGetSymbolAddress((void**)&p_gates, g_gates);

    // ---- one-time precompute ----
    k_transpose<<<(A_*H_ + 255)/256, 256>>>(Hc_w, p_HcT, A_, H_);
    gemm_nt<false><<<dim3(H_/64, A_/64, 1), 256>>>(Wq, p_HcT, nullptr, p_Wcomb, A_, H_, A_, H_);
    k_bqc<<<1, 512>>>(Wq, bq, Hc_b);
    k_wcat<<<(NG*KX)/256, 256>>>(W_ih, W_hh, b_ih, b_hh);
    k_zero<<<(B_*H_)/256, 256>>>();
    gemm_nt<false><<<dim3(A_/64, (B_*S_)/64, 1), 256>>>(feats,  Ic_w, Ic_b, p_keys,  B_*S_, A_, C_, A_);
    gemm_nt<false><<<dim3(A_/64, (B_*S_)/64, 1), 256>>>(p_keys, Wk,   bk,   p_kproj, B_*S_, A_, A_, A_);

    // ---- 128 sequential decode steps ----
    for (int t = 0; t < T_; t++) {
        k_step_init<<<B_, 256>>>(t, labels, W_ih, bout, out);
        gemm_nt<true><<<dim3(A_/64, B_/64, 8), 256>>>(p_h, p_Wcomb, nullptr, p_qw, B_, A_, H_, A_);
        k_attention<<<B_, 256>>>(va);
        gemm_nt<true><<<dim3(NG/64, B_/64, 4), 256>>>(p_X, p_Wcat, nullptr, p_gates, B_, NG, KX, NG);
        k_cell<<<(B_*H_)/256, 256>>>();
        gemm_nt<true><<<dim3(V_/64, B_/64, 4), 256>>>(p_h, Wout, nullptr, out + (size_t)t * V_, B_, V_, H_, T_*V_);
    }
}

// round 2
// speedup vs baseline: 1.7372x; 1.7372x over previous
#include <cuda_runtime.h>
#include <cuda_fp16.h>
#include <cstdint>

#define B_ 128
#define S_ 256
#define C_ 512
#define T_ 128
#define V_ 256
#define H_ 512
#define A_ 512
#define NG 2048   /* 4*H */
#define KX 1024   /* A + H */
#define NBLK 128

// ---------------- device scratch ----------------
__device__ float  g_keys   [B_*S_*A_];   // fp32 keys (input to kproj GEMM)
__device__ __half g_keys16 [B_*S_*A_];   // fp16 keys for context
__device__ __half g_kproj16[B_*S_*A_];   // fp16 k_proj for scores
__device__ float  g_HcT    [H_*A_];
__device__ float  g_Wcomb  [A_*H_];      // Wq @ Hc_w
__device__ float  g_bqc    [A_];         // bq + Wq @ Hc_b
__device__ float  g_WcatIl [NG*KX];      // interleaved-gate [ W_ih[:,V:] | W_hh ]
__device__ float  g_bcombIl[NG];
__device__ float  g_WihVTil[V_*NG];      // W_ih[:, :V] transposed + interleaved
__device__ float  g_h      [B_*H_];
__device__ float  g_c      [B_*H_];
__device__ float  g_X      [B_*KX];      // [ctx | h]
__device__ float  g_qw     [B_*A_];
__device__ float  g_gates  [B_*NG];      // interleaved: [b][4*j+gate]
__device__ unsigned g_sync;
__device__ unsigned g_tilectr[16];

// ---------------- helpers ----------------
__device__ __forceinline__ void ffma2(float2 &c, float2 a, float2 b) {
    asm("fma.rn.f32x2 %0, %1, %2, %0;"
        : "+l"(reinterpret_cast<unsigned long long&>(c))
        : "l"(reinterpret_cast<unsigned long long&>(a)),
          "l"(reinterpret_cast<unsigned long long&>(b)));
}
__device__ __forceinline__ float wsum(float v) {
    #pragma unroll
    for (int o = 16; o > 0; o >>= 1) v += __shfl_down_sync(0xffffffffu, v, o);
    return v;
}
__device__ __forceinline__ float wmax(float v) {
    #pragma unroll
    for (int o = 16; o > 0; o >>= 1) v = fmaxf(v, __shfl_down_sync(0xffffffffu, v, o));
    return v;
}
__device__ __forceinline__ float sigm(float x) { return 1.f / (1.f + expf(-x)); }

// ---------------- precompute GEMM (256 thr, 64x64 tile, NT) ----------------
// OM=0: C fp32; OM=1: C fp32 + Ch fp16; OM=2: Ch fp16 only
template<int OM>
__global__ void gemm_pre(const float* __restrict__ A, const float* __restrict__ Bm,
                         const float* __restrict__ bias, float* __restrict__ C,
                         __half* __restrict__ Ch, int M, int N, int K, int ldc)
{
    __shared__ __align__(16) float As[16][68];
    __shared__ __align__(16) float Bs[16][68];
    const int tid = threadIdx.x;
    const int tx = tid & 15, ty = tid >> 4;
    const int n0 = blockIdx.x * 64, m0 = blockIdx.y * 64;

    float2 acc[4][2];
    #pragma unroll
    for (int i = 0; i < 4; i++) { acc[i][0] = make_float2(0.f,0.f); acc[i][1] = make_float2(0.f,0.f); }

    const int lr = tid >> 2, lc = (tid & 3) * 4;
    for (int kb = 0; kb < K; kb += 16) {
        float4 av = *(const float4*)(A  + (size_t)(m0 + lr) * K + kb + lc);
        float4 bv = *(const float4*)(Bm + (size_t)(n0 + lr) * K + kb + lc);
        As[lc+0][lr] = av.x; As[lc+1][lr] = av.y; As[lc+2][lr] = av.z; As[lc+3][lr] = av.w;
        Bs[lc+0][lr] = bv.x; Bs[lc+1][lr] = bv.y; Bs[lc+2][lr] = bv.z; Bs[lc+3][lr] = bv.w;
        __syncthreads();
        #pragma unroll
        for (int kk = 0; kk < 16; kk++) {
            float4 a4 = *(const float4*)&As[kk][ty * 4];
            float4 b4 = *(const float4*)&Bs[kk][tx * 4];
            float2 b0 = make_float2(b4.x, b4.y), b1 = make_float2(b4.z, b4.w);
            float a_[4] = {a4.x, a4.y, a4.z, a4.w};
            #pragma unroll
            for (int i = 0; i < 4; i++) {
                float2 aa = make_float2(a_[i], a_[i]);
                ffma2(acc[i][0], aa, b0);
                ffma2(acc[i][1], aa, b1);
            }
        }
        __syncthreads();
    }
    #pragma unroll
    for (int i = 0; i < 4; i++) {
        int m = m0 + ty * 4 + i;
        float vals[4] = {acc[i][0].x, acc[i][0].y, acc[i][1].x, acc[i][1].y};
        #pragma unroll
        for (int j = 0; j < 4; j++) {
            int n = n0 + tx * 4 + j;
            float v = vals[j] + (bias ? bias[n] : 0.f);
            if (OM != 2) C[(size_t)m * ldc + n] = v;
            if (OM >= 1) Ch[(size_t)m * ldc + n] = __float2half(v);
        }
    }
}

// ---------------- one-time prep ----------------
__global__ void k_transpose(const float* __restrict__ W, float* __restrict__ Wt,
                            int R, int Ccols) {
    int idx = blockIdx.x * 256 + threadIdx.x;
    if (idx < R * Ccols) {
        int r = idx / Ccols, c = idx % Ccols;
        Wt[(size_t)c * R + r] = W[idx];
    }
}
__global__ void k_bqc(const float* __restrict__ Wq, const float* __restrict__ bq,
                      const float* __restrict__ Hcb) {
    int a = threadIdx.x;
    float s = bq[a];
    for (int m = 0; m < A_; m++) s += Wq[a * A_ + m] * Hcb[m];
    g_bqc[a] = s;
}
__global__ void k_wcat_il(const float* __restrict__ W_ih, const float* __restrict__ W_hh,
                          const float* __restrict__ b_ih, const float* __restrict__ b_hh) {
    int idx = blockIdx.x * 256 + threadIdx.x;     // NG*KX threads
    int nil = idx >> 10, k = idx & 1023;
    int n = (nil & 3) * H_ + (nil >> 2);
    g_WcatIl[idx] = (k < A_) ? W_ih[(size_t)n * (V_ + A_) + V_ + k]
                             : W_hh[(size_t)n * H_ + (k - A_)];
    if (idx < NG) {
        int nn = (idx & 3) * H_ + (idx >> 2);
        g_bcombIl[idx] = b_ih[nn] + b_hh[nn];
    }
}
__global__ void k_wihvt(const float* __restrict__ W_ih) {
    int idx = blockIdx.x * 256 + threadIdx.x;     // V*NG threads
    int v = idx >> 11, nil = idx & 2047;
    int n = (nil & 3) * H_ + (nil >> 2);
    g_WihVTil[idx] = W_ih[(size_t)n * (V_ + A_) + v];
}
__global__ void k_zero() {
    int idx = blockIdx.x * 256 + threadIdx.x;     // B*H threads
    g_h[idx] = 0.f; g_c[idx] = 0.f;
    int b = idx >> 9, j = idx & 511;
    g_X[b * KX + A_ + j] = 0.f;
    if (idx == 0) g_sync = 0u;
    if (idx < 16) g_tilectr[idx] = 0u;
}

// ---------------- persistent kernel ----------------
__device__ __forceinline__ void gridsync(unsigned &sc) {
    __syncthreads();
    if (threadIdx.x == 0) {
        __threadfence();
        sc += NBLK;
        atomicAdd(&g_sync, 1u);
        while (*(volatile unsigned*)&g_sync < sc) { }
        __threadfence();
    }
    __syncthreads();
}

// C[m][n0+n] = sum_k A[m][k]*Bw[n0+n][k] + bias[n0+n]; 128 x 64 tile, 1024 thr
__device__ __forceinline__ void tile128x64(const float* __restrict__ A, int lda,
        const float* __restrict__ Bw, int ldb, int n0, int K,
        const float* __restrict__ bias, float* __restrict__ Cb, int crs,
        float* sAs, float* sBs)
{
    const int tid = threadIdx.x;
    float2 acc[4];
    #pragma unroll
    for (int i = 0; i < 4; i++) acc[i] = make_float2(0.f, 0.f);
    const int arow = tid >> 3, acol = (tid & 7) * 2;
    const int tx = tid & 31, ty = tid >> 5;

    for (int kb = 0; kb < K; kb += 16) {
        float2 av = *(const float2*)(A + (size_t)arow * lda + kb + acol);
        sAs[acol * 132 + arow] = av.x; sAs[(acol + 1) * 132 + arow] = av.y;
        if (tid < 512) {
            int brow = tid >> 3, bcol = (tid & 7) * 2;
            float2 bv = *(const float2*)(Bw + (size_t)(n0 + brow) * ldb + kb + bcol);
            sBs[bcol * 132 + brow] = bv.x; sBs[(bcol + 1) * 132 + brow] = bv.y;
        }
        __syncthreads();
        #pragma unroll
        for (int kk = 0; kk < 16; kk++) {
            float4 a4 = *(const float4*)(sAs + kk * 132 + ty * 4);
            float2 b2 = *(const float2*)(sBs + kk * 132 + tx * 2);
            ffma2(acc[0], make_float2(a4.x, a4.x), b2);
            ffma2(acc[1], make_float2(a4.y, a4.y), b2);
            ffma2(acc[2], make_float2(a4.z, a4.z), b2);
            ffma2(acc[3], make_float2(a4.w, a4.w), b2);
        }
        __syncthreads();
    }
    int n = n0 + tx * 2;
    float2 bb = make_float2(bias[n], bias[n + 1]);
    #pragma unroll
    for (int i = 0; i < 4; i++) {
        float2 v = make_float2(acc[i].x + bb.x, acc[i].y + bb.y);
        *(float2*)(Cb + (size_t)(ty * 4 + i) * crs + n) = v;
    }
}

__global__ void __launch_bounds__(1024, 1) persist(
        const int* __restrict__ labels, const float* __restrict__ va,
        const float* __restrict__ Wout, const float* __restrict__ bout,
        float* __restrict__ out)
{
    __shared__ __align__(16) float sAs[16 * 132];
    __shared__ __align__(16) float sBs[16 * 132];
    __shared__ __align__(16) float sQ[A_];
    __shared__ __align__(16) float sVa[A_];
    __shared__ float sS[S_];
    __shared__ float sRed[8];
    __shared__ float sRedB[8];
    __shared__ __align__(16) float2 sCtx[4][256];
    __shared__ int sLast;

    const int bid = blockIdx.x, tid = threadIdx.x;
    const int lane = tid & 31, wp = tid >> 5;
    if (tid < A_) sVa[tid] = va[tid];
    unsigned sc = 0;

    for (int t = 0; t < T_; t++) {
        // ---- PA: qw GEMM (jobs 0-7), out GEMM for t-1 (jobs 8-11), gates init (16-47)
        if (bid < 8) {
            tile128x64(g_h, H_, g_Wcomb, H_, bid * 64, H_, g_bqc, g_qw, A_, sAs, sBs);
        } else if (bid < 12) {
            if (t > 0)
                tile128x64(g_h, H_, Wout, H_, (bid - 8) * 64, H_, bout,
                           out + (size_t)(t - 1) * V_, T_ * V_, sAs, sBs);
        } else if (bid >= 16 && bid < 48) {
            int jb = bid - 16;
            #pragma unroll
            for (int i = 0; i < 4; i++) {
                int b = jb * 4 + i;
                int lbl = labels[b * T_ + (t > 0 ? t - 1 : 0)];
                #pragma unroll
                for (int r = 0; r < 2; r++) {
                    int n = tid + r * 1024;
                    g_gates[(size_t)b * NG + n] = g_bcombIl[n] + g_WihVTil[(size_t)lbl * NG + n];
                }
            }
        }
        gridsync(sc);

        // ---- PB: attention for b = bid ----
        {
            const int b = bid;
            if (tid < A_) sQ[tid] = g_qw[b * A_ + tid];
            __syncthreads();
            const float2* sQ2 = (const float2*)sQ;
            const float2* sV2 = (const float2*)sVa;
            const __half2* kp = (const __half2*)g_kproj16 + (size_t)b * S_ * (A_ / 2);
            #pragma unroll 1
            for (int r = 0; r < 8; r++) {
                int j = wp * 8 + r;
                const __half2* row = kp + (size_t)j * (A_ / 2);
                float acc = 0.f;
                #pragma unroll
                for (int k = 0; k < 8; k++) {
                    int p = lane + 32 * k;
                    float2 kv = __half22float2(row[p]);
                    float2 q = sQ2[p], vv = sV2[p];
                    acc = fmaf(vv.x, tanhf(kv.x + q.x), acc);
                    acc = fmaf(vv.y, tanhf(kv.y + q.y), acc);
                }
                acc = wsum(acc);
                if (lane == 0) sS[j] = acc;
            }
            __syncthreads();
            float v = 0.f, e = 0.f;
            if (tid < 256) {
                v = sS[tid];
                float m = wmax(v);
                if (lane == 0) sRed[wp] = m;
            }
            __syncthreads();
            if (tid < 256) {
                float m = sRed[0];
                #pragma unroll
                for (int i = 1; i < 8; i++) m = fmaxf(m, sRed[i]);
                e = expf(v - m);
                float s = wsum(e);
                if (lane == 0) sRedB[wp] = s;
            }
            __syncthreads();
            if (tid < 256) {
                float s = sRedB[0];
                #pragma unroll
                for (int i = 1; i < 8; i++) s += sRedB[i];
                sS[tid] = e / s;
            }
            __syncthreads();
            // context
            int p = tid & 255, q4 = tid >> 8;
            const __half2* kb = (const __half2*)g_keys16 + (size_t)b * S_ * (A_ / 2) + p;
            float2 acc2 = make_float2(0.f, 0.f);
            #pragma unroll 4
            for (int j0 = 0; j0 < 64; j0++) {
                int j = q4 * 64 + j0;
                float w = sS[j];
                float2 kv = __half22float2(kb[(size_t)j * (A_ / 2)]);
                acc2.x = fmaf(w, kv.x, acc2.x);
                acc2.y = fmaf(w, kv.y, acc2.y);
            }
            sCtx[q4][p] = acc2;
            __syncthreads();
            if (tid < 256) {
                float2 a = sCtx[0][tid], b2 = sCtx[1][tid], c2 = sCtx[2][tid], d2 = sCtx[3][tid];
                float2 sres = make_float2(a.x + b2.x + c2.x + d2.x, a.y + b2.y + c2.y + d2.y);
                *(float2*)(g_X + (size_t)b * KX + 2 * tid) = sres;
            }
        }
        gridsync(sc);

        // ---- PC: gates GEMM split-K8 (128 jobs) + fused cell by last finisher ----
        {
            const int nt = bid & 15, ks = bid >> 4;
            const int n0 = nt * 128, k0 = ks * 128;
            float2 acc[4][2];
            #pragma unroll
            for (int i = 0; i < 4; i++) { acc[i][0] = make_float2(0.f,0.f); acc[i][1] = make_float2(0.f,0.f); }
            const int arow = tid >> 3, acol = (tid & 7) * 2;
            const int tx = tid & 31, ty = tid >> 5;
            for (int kb = k0; kb < k0 + 128; kb += 16) {
                float2 av = *(const float2*)(g_X + (size_t)arow * KX + kb + acol);
                sAs[acol * 132 + arow] = av.x; sAs[(acol + 1) * 132 + arow] = av.y;
                float2 bv = *(const float2*)(g_WcatIl + (size_t)(n0 + arow) * KX + kb + acol);
                sBs[acol * 132 + arow] = bv.x; sBs[(acol + 1) * 132 + arow] = bv.y;
                __syncthreads();
                #pragma unroll
                for (int kk = 0; kk < 16; kk++) {
                    float4 a4 = *(const float4*)(sAs + kk * 132 + ty * 4);
                    float4 b4 = *(const float4*)(sBs + kk * 132 + tx * 4);
                    float2 b0 = make_float2(b4.x, b4.y), b1 = make_float2(b4.z, b4.w);
                    ffma2(acc[0][0], make_float2(a4.x, a4.x), b0);
                    ffma2(acc[0][1], make_float2(a4.x, a4.x), b1);
                    ffma2(acc[1][0], make_float2(a4.y, a4.y), b0);
                    ffma2(acc[1][1], make_float2(a4.y, a4.y), b1);
                    ffma2(acc[2][0], make_float2(a4.z, a4.z), b0);
                    ffma2(acc[2][1], make_float2(a4.z, a4.z), b1);
                    ffma2(acc[3][0], make_float2(a4.w, a4.w), b0);
                    ffma2(acc[3][1], make_float2(a4.w, a4.w), b1);
                }
                __syncthreads();
            }
            int n = n0 + tx * 4;
            #pragma unroll
            for (int i = 0; i < 4; i++) {
                float* gp = g_gates + (size_t)(ty * 4 + i) * NG + n;
                atomicAdd(gp + 0, acc[i][0].x);
                atomicAdd(gp + 1, acc[i][0].y);
                atomicAdd(gp + 2, acc[i][1].x);
                atomicAdd(gp + 3, acc[i][1].y);
            }
            __syncthreads();
            if (tid == 0) {
                __threadfence();
                unsigned r = atomicAdd(&g_tilectr[nt], 1u);
                sLast = (r == 7u);
                if (r == 7u) g_tilectr[nt] = 0u;
                __threadfence();
            }
            __syncthreads();
            if (sLast) {
                int jj = tid & 31, b0 = tid >> 5;
                #pragma unroll
                for (int r = 0; r < 4; r++) {
                    int b = b0 + r * 32;
                    int j = nt * 32 + jj;
                    float4 gt = __ldcg((const float4*)(g_gates + (size_t)b * NG + 4 * j));
                    float c = __ldcg(g_c + b * H_ + j);
                    float cn = sigm(gt.y) * c + sigm(gt.x) * tanhf(gt.z);
                    float hn = sigm(gt.w) * tanhf(cn);
                    g_c[b * H_ + j] = cn;
                    g_h[b * H_ + j] = hn;
                    g_X[(size_t)b * KX + A_ + j] = hn;
                }
            }
        }
        gridsync(sc);
    }

    // final out row: out[:, T-1, :] = h @ Wout^T + bout
    if (bid < 4)
        tile128x64(g_h, H_, Wout, H_, bid * 64, H_, bout,
                   out + (size_t)(T_ - 1) * V_, T_ * V_, sAs, sBs);
}

// ---------------- host driver ----------------
extern "C" void kernel_launch(void* const* d_in, const int* in_sizes, int n_in,
                              void* d_out, int out_size) {
    (void)in_sizes; (void)n_in; (void)out_size;
    const float* feats = (const float*)d_in[0];
    const int*   labels= (const int*)  d_in[1];
    const float* Ic_w  = (const float*)d_in[2];
    const float* Ic_b  = (const float*)d_in[3];
    const float* Hc_w  = (const float*)d_in[4];
    const float* Hc_b  = (const float*)d_in[5];
    const float* Wq    = (const float*)d_in[6];
    const float* bq    = (const float*)d_in[7];
    const float* Wk    = (const float*)d_in[8];
    const float* bk    = (const float*)d_in[9];
    const float* va    = (const float*)d_in[10];
    const float* W_ih  = (const float*)d_in[11];
    const float* b_ih  = (const float*)d_in[12];
    const float* W_hh  = (const float*)d_in[13];
    const float* b_hh  = (const float*)d_in[14];
    const float* Wout  = (const float*)d_in[15];
    const float* bout  = (const float*)d_in[16];
    float* out = (float*)d_out;

    float *p_keys, *p_HcT, *p_Wcomb;
    __half *p_keys16, *p_kproj16;
    cudaGetSymbolAddress((void**)&p_keys,    g_keys);
    cudaGetSymbolAddress((void**)&p_keys16,  g_keys16);
    cudaGetSymbolAddress((void**)&p_kproj16, g_kproj16);
    cudaGetSymbolAddress((void**)&p_HcT,     g_HcT);
    cudaGetSymbolAddress((void**)&p_Wcomb,   g_Wcomb);

    // one-time precompute
    k_transpose<<<(A_*H_ + 255)/256, 256>>>(Hc_w, p_HcT, A_, H_);
    gemm_pre<0><<<dim3(H_/64, A_/64), 256>>>(Wq, p_HcT, nullptr, p_Wcomb, nullptr, A_, H_, A_, H_);
    k_bqc<<<1, 512>>>(Wq, bq, Hc_b);
    k_wcat_il<<<(NG*KX)/256, 256>>>(W_ih, W_hh, b_ih, b_hh);
    k_wihvt<<<(V_*NG)/256, 256>>>(W_ih);
    k_zero<<<(B_*H_)/256, 256>>>();
    gemm_pre<1><<<dim3(A_/64, (B_*S_)/64), 256>>>(feats,  Ic_w, Ic_b, p_keys, p_keys16,  B_*S_, A_, C_, A_);
    gemm_pre<2><<<dim3(A_/64, (B_*S_)/64), 256>>>(p_keys, Wk,   bk,   nullptr, p_kproj16, B_*S_, A_, A_, A_);

    // persistent decode: all 128 steps, 3 grid-syncs per step
    persist<<<NBLK, 1024>>>(labels, va, Wout, bout, out);
}

// round 3
// speedup vs baseline: 2.7391x; 1.5767x over previous
#include <cuda_runtime.h>
#include <cuda_fp16.h>
#include <cstdint>

#define B_ 128
#define S_ 256
#define C_ 512
#define T_ 128
#define V_ 256
#define H_ 512
#define A_ 512
#define NG 2048   /* 4*H */
#define KX 1024   /* A + H */
#define NBLK 128

// ---------------- device scratch ----------------
__device__ float  g_keys   [B_*S_*A_];
__device__ __half g_keys16 [B_*S_*A_];
__device__ __half g_kproj16[B_*S_*A_];
__device__ float  g_HcT    [H_*A_];
__device__ float  g_Wcomb  [A_*H_];      // Wq @ Hc_w
__device__ float  g_bqc    [A_];         // bq + Wq @ Hc_b
__device__ float  g_WcatIl [NG*KX];      // interleaved-gate [ W_ih[:,V:] | W_hh ]
__device__ float  g_bcombIl[NG];
__device__ float  g_WihVTil[V_*NG];      // W_ih[:, :V] transposed + interleaved
__device__ float  g_h      [B_*H_];
__device__ float  g_c      [B_*H_];
__device__ float  g_X      [B_*KX];      // [ctx | h]
__device__ float  g_qwp    [8][B_][A_];  // qw split-K partials
__device__ float  g_gpart  [8][B_][NG];  // gates split-K partials (8 MB)
__device__ unsigned g_sync;
__device__ unsigned g_tilectr[16];

// ---------------- helpers ----------------
__device__ __forceinline__ void ffma2(float2 &c, float2 a, float2 b) {
    asm("fma.rn.f32x2 %0, %1, %2, %0;"
        : "+l"(reinterpret_cast<unsigned long long&>(c))
        : "l"(reinterpret_cast<unsigned long long&>(a)),
          "l"(reinterpret_cast<unsigned long long&>(b)));
}
__device__ __forceinline__ float wsum(float v) {
    #pragma unroll
    for (int o = 16; o > 0; o >>= 1) v += __shfl_down_sync(0xffffffffu, v, o);
    return v;
}
__device__ __forceinline__ float wmax(float v) {
    #pragma unroll
    for (int o = 16; o > 0; o >>= 1) v = fmaxf(v, __shfl_down_sync(0xffffffffu, v, o));
    return v;
}
__device__ __forceinline__ float sigm(float x) { return 1.f / (1.f + expf(-x)); }
__device__ __forceinline__ float tanhfast(float x) {
    float y; asm("tanh.approx.f32 %0, %1;" : "=f"(y) : "f"(x)); return y;
}

// ---------------- precompute GEMM (256 thr, 64x64 tile, NT) ----------------
template<int OM>  // 0: fp32 C; 1: fp32 C + fp16 Ch; 2: fp16 Ch only
__global__ void gemm_pre(const float* __restrict__ A, const float* __restrict__ Bm,
                         const float* __restrict__ bias, float* __restrict__ C,
                         __half* __restrict__ Ch, int M, int N, int K, int ldc)
{
    __shared__ __align__(16) float As[16][68];
    __shared__ __align__(16) float Bs[16][68];
    const int tid = threadIdx.x;
    const int tx = tid & 15, ty = tid >> 4;
    const int n0 = blockIdx.x * 64, m0 = blockIdx.y * 64;

    float2 acc[4][2];
    #pragma unroll
    for (int i = 0; i < 4; i++) { acc[i][0] = make_float2(0.f,0.f); acc[i][1] = make_float2(0.f,0.f); }

    const int lr = tid >> 2, lc = (tid & 3) * 4;
    for (int kb = 0; kb < K; kb += 16) {
        float4 av = *(const float4*)(A  + (size_t)(m0 + lr) * K + kb + lc);
        float4 bv = *(const float4*)(Bm + (size_t)(n0 + lr) * K + kb + lc);
        As[lc+0][lr] = av.x; As[lc+1][lr] = av.y; As[lc+2][lr] = av.z; As[lc+3][lr] = av.w;
        Bs[lc+0][lr] = bv.x; Bs[lc+1][lr] = bv.y; Bs[lc+2][lr] = bv.z; Bs[lc+3][lr] = bv.w;
        __syncthreads();
        #pragma unroll
        for (int kk = 0; kk < 16; kk++) {
            float4 a4 = *(const float4*)&As[kk][ty * 4];
            float4 b4 = *(const float4*)&Bs[kk][tx * 4];
            float2 b0 = make_float2(b4.x, b4.y), b1 = make_float2(b4.z, b4.w);
            float a_[4] = {a4.x, a4.y, a4.z, a4.w};
            #pragma unroll
            for (int i = 0; i < 4; i++) {
                float2 aa = make_float2(a_[i], a_[i]);
                ffma2(acc[i][0], aa, b0);
                ffma2(acc[i][1], aa, b1);
            }
        }
        __syncthreads();
    }
    #pragma unroll
    for (int i = 0; i < 4; i++) {
        int m = m0 + ty * 4 + i;
        float vals[4] = {acc[i][0].x, acc[i][0].y, acc[i][1].x, acc[i][1].y};
        #pragma unroll
        for (int j = 0; j < 4; j++) {
            int n = n0 + tx * 4 + j;
            float v = vals[j] + (bias ? bias[n] : 0.f);
            if (OM != 2) C[(size_t)m * ldc + n] = v;
            if (OM >= 1) Ch[(size_t)m * ldc + n] = __float2half(v);
        }
    }
}

// ---------------- one-time prep ----------------
__global__ void k_transpose(const float* __restrict__ W, float* __restrict__ Wt,
                            int R, int Ccols) {
    int idx = blockIdx.x * 256 + threadIdx.x;
    if (idx < R * Ccols) {
        int r = idx / Ccols, c = idx % Ccols;
        Wt[(size_t)c * R + r] = W[idx];
    }
}
__global__ void k_bqc(const float* __restrict__ Wq, const float* __restrict__ bq,
                      const float* __restrict__ Hcb) {
    int a = threadIdx.x;
    float s = bq[a];
    for (int m = 0; m < A_; m++) s += Wq[a * A_ + m] * Hcb[m];
    g_bqc[a] = s;
}
__global__ void k_wcat_il(const float* __restrict__ W_ih, const float* __restrict__ W_hh,
                          const float* __restrict__ b_ih, const float* __restrict__ b_hh) {
    int idx = blockIdx.x * 256 + threadIdx.x;     // NG*KX threads
    int nil = idx >> 10, k = idx & 1023;
    int n = (nil & 3) * H_ + (nil >> 2);
    g_WcatIl[idx] = (k < A_) ? W_ih[(size_t)n * (V_ + A_) + V_ + k]
                             : W_hh[(size_t)n * H_ + (k - A_)];
    if (idx < NG) {
        int nn = (idx & 3) * H_ + (idx >> 2);
        g_bcombIl[idx] = b_ih[nn] + b_hh[nn];
    }
}
__global__ void k_wihvt(const float* __restrict__ W_ih) {
    int idx = blockIdx.x * 256 + threadIdx.x;     // V*NG threads
    int v = idx >> 11, nil = idx & 2047;
    int n = (nil & 3) * H_ + (nil >> 2);
    g_WihVTil[idx] = W_ih[(size_t)n * (V_ + A_) + v];
}
__global__ void k_zero() {
    int idx = blockIdx.x * 256 + threadIdx.x;     // B*H threads
    g_h[idx] = 0.f; g_c[idx] = 0.f;
    int b = idx >> 9, j = idx & 511;
    g_X[b * KX + A_ + j] = 0.f;
    if (idx == 0) g_sync = 0u;
    if (idx < 16) g_tilectr[idx] = 0u;
}

// ---------------- persistent kernel ----------------
__device__ __forceinline__ void gridsync(unsigned &sc) {
    __syncthreads();
    sc += NBLK;
    if (threadIdx.x == 0) {
        asm volatile("red.release.gpu.add.u32 [%0], 1;" :: "l"(&g_sync) : "memory");
        unsigned v;
        do {
            asm volatile("ld.acquire.gpu.u32 %0, [%1];" : "=r"(v) : "l"(&g_sync) : "memory");
        } while (v < sc);
    }
    __syncthreads();
}

// 128m x 64n tile over K slice [k0, k0+klen); ATOM: atomicAdd into C, else plain store
template<bool ATOM>
__device__ __forceinline__ void tile128x64(const float* __restrict__ A, int lda,
        const float* __restrict__ Bw, int ldb, int n0, int k0, int klen,
        float* __restrict__ C, int ldc, float* sAs, float* sBs)
{
    const int tid = threadIdx.x;
    float2 acc[4];
    #pragma unroll
    for (int i = 0; i < 4; i++) acc[i] = make_float2(0.f, 0.f);
    const int arow = tid >> 3, acol = (tid & 7) * 2;
    const int tx = tid & 31, ty = tid >> 5;

    for (int kb = k0; kb < k0 + klen; kb += 16) {
        float2 av = *(const float2*)(A + (size_t)arow * lda + kb + acol);
        sAs[acol * 132 + arow] = av.x; sAs[(acol + 1) * 132 + arow] = av.y;
        if (tid < 512) {
            int brow = tid >> 3, bcol = (tid & 7) * 2;
            float2 bv = *(const float2*)(Bw + (size_t)(n0 + brow) * ldb + kb + bcol);
            sBs[bcol * 132 + brow] = bv.x; sBs[(bcol + 1) * 132 + brow] = bv.y;
        }
        __syncthreads();
        #pragma unroll
        for (int kk = 0; kk < 16; kk++) {
            float4 a4 = *(const float4*)(sAs + kk * 132 + ty * 4);
            float2 b2 = *(const float2*)(sBs + kk * 132 + tx * 2);
            ffma2(acc[0], make_float2(a4.x, a4.x), b2);
            ffma2(acc[1], make_float2(a4.y, a4.y), b2);
            ffma2(acc[2], make_float2(a4.z, a4.z), b2);
            ffma2(acc[3], make_float2(a4.w, a4.w), b2);
        }
        __syncthreads();
    }
    int n = n0 + tx * 2;
    #pragma unroll
    for (int i = 0; i < 4; i++) {
        float* cp = C + (size_t)(ty * 4 + i) * ldc + n;
        if (ATOM) { atomicAdd(cp, acc[i].x); atomicAdd(cp + 1, acc[i].y); }
        else      { *(float2*)cp = acc[i]; }
    }
}

__global__ void __launch_bounds__(1024, 1) persist(
        const int* __restrict__ labels, const float* __restrict__ va,
        const float* __restrict__ Wout, const float* __restrict__ bout,
        float* __restrict__ out)
{
    __shared__ __align__(16) float sAs[16 * 132];
    __shared__ __align__(16) float sBs[16 * 132];
    __shared__ __align__(16) float sQ[A_];
    __shared__ __align__(16) float sVa[A_];
    __shared__ float sS[S_];
    __shared__ float sRed[8];
    __shared__ float sRedB[8];
    __shared__ __align__(16) float2 sCtx[4][256];
    __shared__ int sLast;

    const int bid = blockIdx.x, tid = threadIdx.x;
    const int lane = tid & 31, wp = tid >> 5;
    if (tid < A_) sVa[tid] = va[tid];
    unsigned sc = 0;

    for (int t = 0; t < T_; t++) {
        // ======== PA: qw split-K partials (blocks 0-63), out[t-1] GEMM (64-127) ====
        if (bid < 64) {
            int nt = bid & 7, ks = bid >> 3;
            tile128x64<false>(g_h, H_, g_Wcomb, H_, nt * 64, ks * 64, 64,
                              &g_qwp[ks][0][0], A_, sAs, sBs);
        } else if (t > 0) {
            int j = bid - 64, nt = j & 3, ks = j >> 2;   // 16 k-slices of 32
            tile128x64<true>(g_h, H_, Wout, H_, nt * 64, ks * 32, 32,
                             out + (size_t)(t - 1) * V_, T_ * V_, sAs, sBs);
        }
        gridsync(sc);

        // ======== PB: attention for batch b = bid; out-row init =================
        {
            const int b = bid;
            if (tid < A_) {
                float s = g_bqc[tid];
                #pragma unroll
                for (int ks = 0; ks < 8; ks++) s += g_qwp[ks][b][tid];
                sQ[tid] = s;
            }
            if (tid < 64) {
                float4 bv = ((const float4*)bout)[tid];
                *(float4*)(out + ((size_t)b * T_ + t) * V_ + tid * 4) = bv;
            }
            __syncthreads();

            // scores: q/va in registers, LDG.128 fp16 kproj, tanh.approx
            float qr[16], vr[16];
            {
                const float4* q4 = (const float4*)(sQ + lane * 16);
                const float4* v4 = (const float4*)(sVa + lane * 16);
                #pragma unroll
                for (int i = 0; i < 4; i++) {
                    float4 qv = q4[i], vv = v4[i];
                    qr[i*4+0]=qv.x; qr[i*4+1]=qv.y; qr[i*4+2]=qv.z; qr[i*4+3]=qv.w;
                    vr[i*4+0]=vv.x; vr[i*4+1]=vv.y; vr[i*4+2]=vv.z; vr[i*4+3]=vv.w;
                }
            }
            #pragma unroll 1
            for (int r = 0; r < 8; r++) {
                int j = wp * 8 + r;
                const uint4* row = (const uint4*)(g_kproj16 + ((size_t)b * S_ + j) * A_);
                uint4 d0 = row[lane * 2];
                uint4 d1 = row[lane * 2 + 1];
                const __half2* h0 = (const __half2*)&d0;
                const __half2* h1 = (const __half2*)&d1;
                float acc = 0.f;
                #pragma unroll
                for (int i = 0; i < 4; i++) {
                    float2 k0 = __half22float2(h0[i]);
                    float2 k1 = __half22float2(h1[i]);
                    acc = fmaf(vr[2*i+0], tanhfast(k0.x + qr[2*i+0]), acc);
                    acc = fmaf(vr[2*i+1], tanhfast(k0.y + qr[2*i+1]), acc);
                    acc = fmaf(vr[8+2*i+0], tanhfast(k1.x + qr[8+2*i+0]), acc);
                    acc = fmaf(vr[8+2*i+1], tanhfast(k1.y + qr[8+2*i+1]), acc);
                }
                acc = wsum(acc);
                if (lane == 0) sS[j] = acc;
            }
            __syncthreads();

            // softmax over S=256
            float v = 0.f, e = 0.f;
            if (tid < 256) {
                v = sS[tid];
                float m = wmax(v);
                if (lane == 0) sRed[wp] = m;
            }
            __syncthreads();
            if (tid < 256) {
                float m = sRed[0];
                #pragma unroll
                for (int i = 1; i < 8; i++) m = fmaxf(m, sRed[i]);
                e = expf(v - m);
                float s = wsum(e);
                if (lane == 0) sRedB[wp] = s;
            }
            __syncthreads();
            if (tid < 256) {
                float s = sRedB[0];
                #pragma unroll
                for (int i = 1; i < 8; i++) s += sRedB[i];
                sS[tid] = e / s;
            }
            __syncthreads();

            // context
            int p = tid & 255, q4i = tid >> 8;
            const __half2* kb = (const __half2*)g_keys16 + (size_t)b * S_ * (A_ / 2) + p;
            float2 acc2 = make_float2(0.f, 0.f);
            #pragma unroll 4
            for (int j0 = 0; j0 < 64; j0++) {
                int j = q4i * 64 + j0;
                float w = sS[j];
                float2 kv = __half22float2(kb[(size_t)j * (A_ / 2)]);
                acc2.x = fmaf(w, kv.x, acc2.x);
                acc2.y = fmaf(w, kv.y, acc2.y);
            }
            sCtx[q4i][p] = acc2;
            __syncthreads();
            if (tid < 256) {
                float2 a = sCtx[0][tid], b2 = sCtx[1][tid], c2 = sCtx[2][tid], d2 = sCtx[3][tid];
                float2 sres = make_float2(a.x + b2.x + c2.x + d2.x, a.y + b2.y + c2.y + d2.y);
                *(float2*)(g_X + (size_t)b * KX + 2 * tid) = sres;
            }
        }
        gridsync(sc);

        // ======== PC: gates GEMM partials + fused reduce/gather/cell ============
        {
            const int nt = bid & 15, ks = bid >> 4;
            const int n0 = nt * 128, k0 = ks * 128;
            float2 acc[4][2];
            #pragma unroll
            for (int i = 0; i < 4; i++) { acc[i][0] = make_float2(0.f,0.f); acc[i][1] = make_float2(0.f,0.f); }
            const int arow = tid >> 3, acol = (tid & 7) * 2;
            const int tx = tid & 31, ty = tid >> 5;
            for (int kb = k0; kb < k0 + 128; kb += 16) {
                float2 av = *(const float2*)(g_X + (size_t)arow * KX + kb + acol);
                sAs[acol * 132 + arow] = av.x; sAs[(acol + 1) * 132 + arow] = av.y;
                float2 bv = *(const float2*)(g_WcatIl + (size_t)(n0 + arow) * KX + kb + acol);
                sBs[acol * 132 + arow] = bv.x; sBs[(acol + 1) * 132 + arow] = bv.y;
                __syncthreads();
                #pragma unroll
                for (int kk = 0; kk < 16; kk++) {
                    float4 a4 = *(const float4*)(sAs + kk * 132 + ty * 4);
                    float4 b4 = *(const float4*)(sBs + kk * 132 + tx * 4);
                    float2 b0 = make_float2(b4.x, b4.y), b1 = make_float2(b4.z, b4.w);
                    ffma2(acc[0][0], make_float2(a4.x, a4.x), b0);
                    ffma2(acc[0][1], make_float2(a4.x, a4.x), b1);
                    ffma2(acc[1][0], make_float2(a4.y, a4.y), b0);
                    ffma2(acc[1][1], make_float2(a4.y, a4.y), b1);
                    ffma2(acc[2][0], make_float2(a4.z, a4.z), b0);
                    ffma2(acc[2][1], make_float2(a4.z, a4.z), b1);
                    ffma2(acc[3][0], make_float2(a4.w, a4.w), b0);
                    ffma2(acc[3][1], make_float2(a4.w, a4.w), b1);
                }
                __syncthreads();
            }
            // plain-store partial tile
            float* gp = &g_gpart[ks][0][0];
            #pragma unroll
            for (int i = 0; i < 4; i++) {
                float4 v4 = make_float4(acc[i][0].x, acc[i][0].y, acc[i][1].x, acc[i][1].y);
                *(float4*)(gp + (size_t)(ty * 4 + i) * NG + n0 + tx * 4) = v4;
            }
            __syncthreads();
            if (tid == 0) {
                __threadfence();
                unsigned r = atomicAdd(&g_tilectr[nt], 1u);
                sLast = (r == 7u);
                if (r == 7u) g_tilectr[nt] = 0u;
            }
            __syncthreads();
            if (sLast) {
                __threadfence();
                int b = tid >> 3, jg = tid & 7;
                int colbase = n0 + jg * 16;
                float4 s0 = make_float4(0,0,0,0), s1 = s0, s2 = s0, s3 = s0;
                #pragma unroll
                for (int k2 = 0; k2 < 8; k2++) {
                    const float4* pp = (const float4*)(&g_gpart[k2][b][colbase]);
                    float4 a0 = pp[0], a1 = pp[1], a2 = pp[2], a3 = pp[3];
                    s0.x+=a0.x; s0.y+=a0.y; s0.z+=a0.z; s0.w+=a0.w;
                    s1.x+=a1.x; s1.y+=a1.y; s1.z+=a1.z; s1.w+=a1.w;
                    s2.x+=a2.x; s2.y+=a2.y; s2.z+=a2.z; s2.w+=a2.w;
                    s3.x+=a3.x; s3.y+=a3.y; s3.z+=a3.z; s3.w+=a3.w;
                }
                int lbl = labels[b * T_ + (t > 0 ? t - 1 : 0)];
                const float4* bc = (const float4*)(g_bcombIl + colbase);
                const float4* wv = (const float4*)(g_WihVTil + (size_t)lbl * NG + colbase);
                float4 b0 = bc[0], b1 = bc[1], b2 = bc[2], b3 = bc[3];
                float4 w0 = wv[0], w1 = wv[1], w2 = wv[2], w3 = wv[3];
                s0.x+=b0.x+w0.x; s0.y+=b0.y+w0.y; s0.z+=b0.z+w0.z; s0.w+=b0.w+w0.w;
                s1.x+=b1.x+w1.x; s1.y+=b1.y+w1.y; s1.z+=b1.z+w1.z; s1.w+=b1.w+w1.w;
                s2.x+=b2.x+w2.x; s2.y+=b2.y+w2.y; s2.z+=b2.z+w2.z; s2.w+=b2.w+w2.w;
                s3.x+=b3.x+w3.x; s3.y+=b3.y+w3.y; s3.z+=b3.z+w3.z; s3.w+=b3.w+w3.w;
                // cell for j = nt*32 + jg*4 + {0..3}; each s = (i,f,g,o)
                int j0 = nt * 32 + jg * 4;
                float4 cold = *(const float4*)(g_c + b * H_ + j0);
                float4 cn, hn;
                cn.x = sigm(s0.y) * cold.x + sigm(s0.x) * tanhf(s0.z);
                cn.y = sigm(s1.y) * cold.y + sigm(s1.x) * tanhf(s1.z);
                cn.z = sigm(s2.y) * cold.z + sigm(s2.x) * tanhf(s2.z);
                cn.w = sigm(s3.y) * cold.w + sigm(s3.x) * tanhf(s3.z);
                hn.x = sigm(s0.w) * tanhf(cn.x);
                hn.y = sigm(s1.w) * tanhf(cn.y);
                hn.z = sigm(s2.w) * tanhf(cn.z);
                hn.w = sigm(s3.w) * tanhf(cn.w);
                *(float4*)(g_c + b * H_ + j0) = cn;
                *(float4*)(g_h + b * H_ + j0) = hn;
                *(float4*)(g_X + (size_t)b * KX + A_ + j0) = hn;
            }
        }
        gridsync(sc);
    }

    // final out row: out[:, T-1, :] += h @ Wout^T  (init was done in PB t=T-1)
    if (bid >= 64) {
        int j = bid - 64, nt = j & 3, ks = j >> 2;
        tile128x64<true>(g_h, H_, Wout, H_, nt * 64, ks * 32, 32,
                         out + (size_t)(T_ - 1) * V_, T_ * V_, sAs, sBs);
    }
}

// ---------------- host driver ----------------
extern "C" void kernel_launch(void* const* d_in, const int* in_sizes, int n_in,
                              void* d_out, int out_size) {
    (void)in_sizes; (void)n_in; (void)out_size;
    const float* feats = (const float*)d_in[0];
    const int*   labels= (const int*)  d_in[1];
    const float* Ic_w  = (const float*)d_in[2];
    const float* Ic_b  = (const float*)d_in[3];
    const float* Hc_w  = (const float*)d_in[4];
    const float* Hc_b  = (const float*)d_in[5];
    const float* Wq    = (const float*)d_in[6];
    const float* bq    = (const float*)d_in[7];
    const float* Wk    = (const float*)d_in[8];
    const float* bk    = (const float*)d_in[9];
    const float* va    = (const float*)d_in[10];
    const float* W_ih  = (const float*)d_in[11];
    const float* b_ih  = (const float*)d_in[12];
    const float* W_hh  = (const float*)d_in[13];
    const float* b_hh  = (const float*)d_in[14];
    const float* Wout  = (const float*)d_in[15];
    const float* bout  = (const float*)d_in[16];
    float* out = (float*)d_out;

    float *p_keys, *p_HcT, *p_Wcomb;
    __half *p_keys16, *p_kproj16;
    cudaGetSymbolAddress((void**)&p_keys,    g_keys);
    cudaGetSymbolAddress((void**)&p_keys16,  g_keys16);
    cudaGetSymbolAddress((void**)&p_kproj16, g_kproj16);
    cudaGetSymbolAddress((void**)&p_HcT,     g_HcT);
    cudaGetSymbolAddress((void**)&p_Wcomb,   g_Wcomb);

    // one-time precompute
    k_transpose<<<(A_*H_ + 255)/256, 256>>>(Hc_w, p_HcT, A_, H_);
    gemm_pre<0><<<dim3(H_/64, A_/64), 256>>>(Wq, p_HcT, nullptr, p_Wcomb, nullptr, A_, H_, A_, H_);
    k_bqc<<<1, 512>>>(Wq, bq, Hc_b);
    k_wcat_il<<<(NG*KX)/256, 256>>>(W_ih, W_hh, b_ih, b_hh);
    k_wihvt<<<(V_*NG)/256, 256>>>(W_ih);
    k_zero<<<(B_*H_)/256, 256>>>();
    gemm_pre<1><<<dim3(A_/64, (B_*S_)/64), 256>>>(feats,  Ic_w, Ic_b, p_keys, p_keys16,  B_*S_, A_, C_, A_);
    gemm_pre<2><<<dim3(A_/64, (B_*S_)/64), 256>>>(p_keys, Wk,   bk,   nullptr, p_kproj16, B_*S_, A_, A_, A_);

    // persistent decode: all 128 steps, 3 grid-syncs per step
    persist<<<NBLK, 1024>>>(labels, va, Wout, bout, out);
}

// round 4
// speedup vs baseline: 6.0146x; 2.1958x over previous
#include <cuda_runtime.h>
#include <cuda_fp16.h>
#include <cstdint>

#define B_ 128
#define S_ 256
#define C_ 512
#define T_ 128
#define V_ 256
#define H_ 512
#define A_ 512
#define NG 2048   /* 4*H */
#define KX 1024   /* A + H */
#define NBLK 128

#define SM_B_OFF 32768
#define SM_R_OFF 36864
#define SMEM_DYN 102400   /* 36864 + 8*128*16*4 */

// ---------------- device scratch ----------------
__device__ __half g_feats16[B_*S_*C_];
__device__ __half g_keys16 [B_*S_*A_];
__device__ __half g_kproj16[B_*S_*A_];
__device__ __half g_Icw16  [A_*C_];
__device__ __half g_Wk16   [A_*A_];
__device__ float  g_HcT    [H_*A_];
__device__ __half g_Wcomb16[A_*H_];   // (Wq @ Hc_w) fp16, rows a, cols k
__device__ float  g_bqc    [A_];      // bq + Wq @ Hc_b
__device__ __half g_Wcat16 [NG*KX];   // interleaved-gate [W_ih[:,V:] | W_hh] fp16
__device__ float  g_bcombIl[NG];
__device__ float  g_WihVTil[V_*NG];
__device__ __half g_Wout16 [V_*H_];
__device__ __half g_h16    [B_*H_];
__device__ float  g_c      [B_*H_];
__device__ __half g_Xh     [B_*KX];   // [ctx | h] fp16
__device__ float  g_qw     [B_*A_];
__device__ unsigned g_sync;

// ---------------- helpers ----------------
__device__ __forceinline__ float wsum(float v) {
    #pragma unroll
    for (int o = 16; o > 0; o >>= 1) v += __shfl_down_sync(0xffffffffu, v, o);
    return v;
}
__device__ __forceinline__ float wmax(float v) {
    #pragma unroll
    for (int o = 16; o > 0; o >>= 1) v = fmaxf(v, __shfl_down_sync(0xffffffffu, v, o));
    return v;
}
__device__ __forceinline__ float sigm(float x) { return 1.f / (1.f + expf(-x)); }
__device__ __forceinline__ float tanhfast(float x) {
    float y; asm("tanh.approx.f32 %0, %1;" : "=f"(y) : "f"(x)); return y;
}
__device__ __forceinline__ void ldmx4(uint32_t* r, uint32_t addr) {
    asm volatile("ldmatrix.sync.aligned.m8n8.x4.shared.b16 {%0,%1,%2,%3}, [%4];"
        : "=r"(r[0]), "=r"(r[1]), "=r"(r[2]), "=r"(r[3]) : "r"(addr));
}
__device__ __forceinline__ void ldmx2(uint32_t &r0, uint32_t &r1, uint32_t addr) {
    asm volatile("ldmatrix.sync.aligned.m8n8.x2.shared.b16 {%0,%1}, [%2];"
        : "=r"(r0), "=r"(r1) : "r"(addr));
}
__device__ __forceinline__ void mma16816(float* c, const uint32_t* a, uint32_t b0, uint32_t b1) {
    asm volatile("mma.sync.aligned.m16n8k16.row.col.f32.f16.f16.f32 "
        "{%0,%1,%2,%3}, {%4,%5,%6,%7}, {%8,%9}, {%0,%1,%2,%3};"
        : "+f"(c[0]), "+f"(c[1]), "+f"(c[2]), "+f"(c[3])
        : "r"(a[0]), "r"(a[1]), "r"(a[2]), "r"(a[3]), "r"(b0), "r"(b1));
}

// ---------------- precompute mma GEMM: Ch[M,N] = A[M,K] @ B[N,K]^T + bias ----
// 256 thr, block tile 64x64, fp16 in, fp16 out, fp32 accum. grid=(N/64, M/64)
__global__ void mma_pre(const __half* __restrict__ Ag, const __half* __restrict__ Bg,
                        const float* __restrict__ bias, __half* __restrict__ Ch,
                        int K, int ldc)
{
    __shared__ __align__(16) char sA[64 * 128];
    __shared__ __align__(16) char sB[64 * 128];
    const int tid = threadIdx.x, lane = tid & 31, wid = tid >> 5;
    const int mg = wid >> 2, ng = wid & 3;        // 2 x 4 warps, warp tile m32 x n16
    const int m0 = blockIdx.y * 64, n0 = blockIdx.x * 64;
    uint32_t sa = (uint32_t)__cvta_generic_to_shared(sA);
    uint32_t sb = (uint32_t)__cvta_generic_to_shared(sB);

    float cfr[2][2][4];
    #pragma unroll
    for (int i = 0; i < 2; i++)
        #pragma unroll
        for (int j = 0; j < 2; j++)
            #pragma unroll
            for (int q = 0; q < 4; q++) cfr[i][j][q] = 0.f;

    for (int kc = 0; kc < K / 64; kc++) {
        __syncthreads();
        #pragma unroll
        for (int r = 0; r < 2; r++) {
            int idx = tid + r * 256;
            int row = idx >> 3, ch = idx & 7;
            int chs = ch ^ (row & 7);
            *(uint4*)(sA + row * 128 + chs * 16) =
                *(const uint4*)(Ag + (size_t)(m0 + row) * K + kc * 64 + ch * 8);
            *(uint4*)(sB + row * 128 + chs * 16) =
                *(const uint4*)(Bg + (size_t)(n0 + row) * K + kc * 64 + ch * 8);
        }
        __syncthreads();
        #pragma unroll
        for (int s = 0; s < 4; s++) {
            uint32_t a0[4], a1[4], bb[4];
            int row = mg * 32 + (lane & 15);
            int ch = (s * 2 + (lane >> 4)) ^ (row & 7);
            ldmx4(a0, sa + row * 128 + ch * 16);
            row += 16; ch = (s * 2 + (lane >> 4)) ^ (row & 7);
            ldmx4(a1, sa + row * 128 + ch * 16);
            int n = ng * 16 + ((lane >> 4) << 3) + (lane & 7);
            ch = (s * 2 + ((lane >> 3) & 1)) ^ (n & 7);
            ldmx4(bb, sb + n * 128 + ch * 16);
            mma16816(cfr[0][0], a0, bb[0], bb[1]);
            mma16816(cfr[0][1], a0, bb[2], bb[3]);
            mma16816(cfr[1][0], a1, bb[0], bb[1]);
            mma16816(cfr[1][1], a1, bb[2], bb[3]);
        }
    }
    int g = lane >> 2, t = lane & 3;
    #pragma unroll
    for (int mf = 0; mf < 2; mf++)
        #pragma unroll
        for (int nf = 0; nf < 2; nf++) {
            int row = m0 + mg * 32 + mf * 16 + g;
            int col = n0 + ng * 16 + nf * 8 + 2 * t;
            float b0v = bias ? bias[col] : 0.f, b1v = bias ? bias[col + 1] : 0.f;
            float* c = cfr[mf][nf];
            *(__half2*)(Ch + (size_t)row * ldc + col) =
                __floats2half2_rn(c[0] + b0v, c[1] + b1v);
            *(__half2*)(Ch + (size_t)(row + 8) * ldc + col) =
                __floats2half2_rn(c[2] + b0v, c[3] + b1v);
        }
}

// ---------------- small FFMA GEMM for Wcomb (fp32 in, fp16 out) -------------
__global__ void gemm_wcomb(const float* __restrict__ A, const float* __restrict__ Bm,
                           __half* __restrict__ Ch, int M, int N, int K)
{
    __shared__ __align__(16) float As[16][68];
    __shared__ __align__(16) float Bs[16][68];
    const int tid = threadIdx.x;
    const int tx = tid & 15, ty = tid >> 4;
    const int n0 = blockIdx.x * 64, m0 = blockIdx.y * 64;
    float acc[4][4];
    #pragma unroll
    for (int i = 0; i < 4; i++)
        #pragma unroll
        for (int j = 0; j < 4; j++) acc[i][j] = 0.f;
    const int lr = tid >> 2, lc = (tid & 3) * 4;
    for (int kb = 0; kb < K; kb += 16) {
        float4 av = *(const float4*)(A  + (size_t)(m0 + lr) * K + kb + lc);
        float4 bv = *(const float4*)(Bm + (size_t)(n0 + lr) * K + kb + lc);
        As[lc+0][lr] = av.x; As[lc+1][lr] = av.y; As[lc+2][lr] = av.z; As[lc+3][lr] = av.w;
        Bs[lc+0][lr] = bv.x; Bs[lc+1][lr] = bv.y; Bs[lc+2][lr] = bv.z; Bs[lc+3][lr] = bv.w;
        __syncthreads();
        #pragma unroll
        for (int kk = 0; kk < 16; kk++) {
            float4 a4 = *(const float4*)&As[kk][ty * 4];
            float4 b4 = *(const float4*)&Bs[kk][tx * 4];
            float a_[4] = {a4.x, a4.y, a4.z, a4.w};
            float b_[4] = {b4.x, b4.y, b4.z, b4.w};
            #pragma unroll
            for (int i = 0; i < 4; i++)
                #pragma unroll
                for (int j = 0; j < 4; j++) acc[i][j] = fmaf(a_[i], b_[j], acc[i][j]);
        }
        __syncthreads();
    }
    #pragma unroll
    for (int i = 0; i < 4; i++)
        #pragma unroll
        for (int j = 0; j < 4; j++)
            Ch[(size_t)(m0 + ty * 4 + i) * N + n0 + tx * 4 + j] = __float2half(acc[i][j]);
}

// ---------------- one-time prep ----------------
__global__ void k_cvt(const float* __restrict__ s, __half* __restrict__ d, int n) {
    int i = blockIdx.x * 256 + threadIdx.x;
    if (i < n) d[i] = __float2half(s[i]);
}
__global__ void k_transpose(const float* __restrict__ W, float* __restrict__ Wt,
                            int R, int Ccols) {
    int idx = blockIdx.x * 256 + threadIdx.x;
    if (idx < R * Ccols) {
        int r = idx / Ccols, c = idx % Ccols;
        Wt[(size_t)c * R + r] = W[idx];
    }
}
__global__ void k_bqc(const float* __restrict__ Wq, const float* __restrict__ bq,
                      const float* __restrict__ Hcb) {
    int a = threadIdx.x;
    float s = bq[a];
    for (int m = 0; m < A_; m++) s += Wq[a * A_ + m] * Hcb[m];
    g_bqc[a] = s;
}
__global__ void k_wcat_il(const float* __restrict__ W_ih, const float* __restrict__ W_hh,
                          const float* __restrict__ b_ih, const float* __restrict__ b_hh) {
    int idx = blockIdx.x * 256 + threadIdx.x;     // NG*KX threads
    int nil = idx >> 10, k = idx & 1023;
    int n = (nil & 3) * H_ + (nil >> 2);
    float v = (k < A_) ? W_ih[(size_t)n * (V_ + A_) + V_ + k]
                       : W_hh[(size_t)n * H_ + (k - A_)];
    g_Wcat16[idx] = __float2half(v);
    if (idx < NG) {
        int nn = (idx & 3) * H_ + (idx >> 2);
        g_bcombIl[idx] = b_ih[nn] + b_hh[nn];
    }
}
__global__ void k_wihvt(const float* __restrict__ W_ih) {
    int idx = blockIdx.x * 256 + threadIdx.x;     // V*NG threads
    int v = idx >> 11, nil = idx & 2047;
    int n = (nil & 3) * H_ + (nil >> 2);
    g_WihVTil[idx] = W_ih[(size_t)n * (V_ + A_) + v];
}
__global__ void k_zero() {
    int idx = blockIdx.x * 256 + threadIdx.x;     // B*H threads
    g_h16[idx] = __float2half(0.f);
    g_c[idx] = 0.f;
    int b = idx >> 9, j = idx & 511;
    g_Xh[b * KX + A_ + j] = __float2half(0.f);
    if (idx == 0) g_sync = 0u;
}

// ---------------- persistent kernel ----------------
__device__ __forceinline__ void gridsync(unsigned &sc) {
    __syncthreads();
    sc += NBLK;
    if (threadIdx.x == 0) {
        asm volatile("red.release.gpu.add.u32 [%0], 1;" :: "l"(&g_sync) : "memory");
        unsigned v;
        do {
            asm volatile("ld.acquire.gpu.u32 %0, [%1];" : "=r"(v) : "l"(&g_sync) : "memory");
        } while (v < sc);
    }
    __syncthreads();
}

// mma GEMM: partial sums for C[128, n0..n0+8) = A[128,K] @ B[n0..,K]^T
// into 8 smem k-group buffers of [128][8] f32. 1024 threads.
__device__ __forceinline__ void mma_gemm_n8(const __half* __restrict__ Ag, int lda,
        const __half* __restrict__ Bg, int ldb, int n0, int K,
        char* dyn, uint32_t sb)
{
    const int tid = threadIdx.x, lane = tid & 31, wid = tid >> 5;
    const int mg = wid >> 3, kg = wid & 7;
    float cfr[2][4];
    #pragma unroll
    for (int i = 0; i < 2; i++)
        #pragma unroll
        for (int q = 0; q < 4; q++) cfr[i][q] = 0.f;

    for (int kc = 0; kc < K / 128; kc++) {
        __syncthreads();
        #pragma unroll
        for (int r = 0; r < 2; r++) {
            int idx = tid + r * 1024;
            int row = idx >> 4, ch = idx & 15;
            int chs = ch ^ (row & 7);
            *(uint4*)(dyn + row * 256 + chs * 16) =
                *(const uint4*)(Ag + (size_t)row * lda + kc * 128 + ch * 8);
        }
        if (tid < 128) {
            int row = tid >> 4, ch = tid & 15;
            int chs = ch ^ (row & 7);
            *(uint4*)(dyn + SM_B_OFF + row * 256 + chs * 16) =
                *(const uint4*)(Bg + (size_t)(n0 + row) * ldb + kc * 128 + ch * 8);
        }
        __syncthreads();
        uint32_t a0[4], a1[4], b0, b1;
        int s = kg;
        int row = mg * 32 + (lane & 15);
        int ch = (s * 2 + (lane >> 4)) ^ (row & 7);
        ldmx4(a0, sb + row * 256 + ch * 16);
        row += 16; ch = (s * 2 + (lane >> 4)) ^ (row & 7);
        ldmx4(a1, sb + row * 256 + ch * 16);
        int n = lane & 7;
        ch = (s * 2 + ((lane >> 3) & 1)) ^ (n & 7);
        ldmx2(b0, b1, sb + SM_B_OFF + n * 256 + ch * 16);
        mma16816(cfr[0], a0, b0, b1);
        mma16816(cfr[1], a1, b0, b1);
    }
    float* buf = (float*)(dyn + SM_R_OFF) + kg * (128 * 8);
    int g = lane >> 2, t = lane & 3;
    #pragma unroll
    for (int mf = 0; mf < 2; mf++) {
        int r0 = mg * 32 + mf * 16 + g;
        *(float2*)(buf + r0 * 8 + 2 * t) = make_float2(cfr[mf][0], cfr[mf][1]);
        *(float2*)(buf + (r0 + 8) * 8 + 2 * t) = make_float2(cfr[mf][2], cfr[mf][3]);
    }
    __syncthreads();
}

__global__ void __launch_bounds__(1024, 1) persist(
        const int* __restrict__ labels, const float* __restrict__ va,
        const float* __restrict__ bout, float* __restrict__ out)
{
    extern __shared__ __align__(16) char dyn[];
    const uint32_t sb = (uint32_t)__cvta_generic_to_shared(dyn);
    float* sRbuf = (float*)(dyn + SM_R_OFF);
    float* sQ    = (float*)(dyn + 36864);
    float* sVa   = (float*)(dyn + 38912);
    float* sS    = (float*)(dyn + 39936);
    float* sRed  = (float*)(dyn + 40960);
    float* sRedB = (float*)(dyn + 40992);
    float2* sCtx = (float2*)(dyn + 41024);

    const int bid = blockIdx.x, tid = threadIdx.x;
    const int lane = tid & 31, wp = tid >> 5;
    unsigned sc = 0;

    for (int t = 0; t < T_; t++) {
        // ==== PA: qw (blocks 0-63, n-tile 8), out[t-1] (blocks 64-95, n-tile 8)
        if (bid < 64) {
            int n0 = bid * 8;
            mma_gemm_n8(g_h16, H_, g_Wcomb16, H_, n0, H_, dyn, sb);
            int b = tid >> 3, nl = tid & 7;
            float s = g_bqc[n0 + nl];
            #pragma unroll
            for (int kg = 0; kg < 8; kg++) s += sRbuf[kg * 1024 + b * 8 + nl];
            g_qw[b * A_ + n0 + nl] = s;
        } else if (bid < 96 && t > 0) {
            int n0 = (bid - 64) * 8;
            mma_gemm_n8(g_h16, H_, g_Wout16, H_, n0, H_, dyn, sb);
            int b = tid >> 3, nl = tid & 7;
            float s = bout[n0 + nl];
            #pragma unroll
            for (int kg = 0; kg < 8; kg++) s += sRbuf[kg * 1024 + b * 8 + nl];
            out[((size_t)b * T_ + (t - 1)) * V_ + n0 + nl] = s;
        }
        gridsync(sc);

        // ==== PB: attention for batch b = bid ====
        {
            const int b = bid;
            if (tid < A_) { sQ[tid] = g_qw[b * A_ + tid]; sVa[tid] = va[tid]; }
            __syncthreads();

            float qr[16], vr[16];
            {
                const float4* q4 = (const float4*)(sQ + lane * 16);
                const float4* v4 = (const float4*)(sVa + lane * 16);
                #pragma unroll
                for (int i = 0; i < 4; i++) {
                    float4 qv = q4[i], vv = v4[i];
                    qr[i*4+0]=qv.x; qr[i*4+1]=qv.y; qr[i*4+2]=qv.z; qr[i*4+3]=qv.w;
                    vr[i*4+0]=vv.x; vr[i*4+1]=vv.y; vr[i*4+2]=vv.z; vr[i*4+3]=vv.w;
                }
            }
            #pragma unroll 1
            for (int r = 0; r < 8; r++) {
                int j = wp * 8 + r;
                const uint4* row = (const uint4*)(g_kproj16 + ((size_t)b * S_ + j) * A_);
                uint4 d0 = row[lane * 2];
                uint4 d1 = row[lane * 2 + 1];
                const __half2* h0 = (const __half2*)&d0;
                const __half2* h1 = (const __half2*)&d1;
                float acc = 0.f;
                #pragma unroll
                for (int i = 0; i < 4; i++) {
                    float2 k0 = __half22float2(h0[i]);
                    float2 k1 = __half22float2(h1[i]);
                    acc = fmaf(vr[2*i+0], tanhfast(k0.x + qr[2*i+0]), acc);
                    acc = fmaf(vr[2*i+1], tanhfast(k0.y + qr[2*i+1]), acc);
                    acc = fmaf(vr[8+2*i+0], tanhfast(k1.x + qr[8+2*i+0]), acc);
                    acc = fmaf(vr[8+2*i+1], tanhfast(k1.y + qr[8+2*i+1]), acc);
                }
                acc = wsum(acc);
                if (lane == 0) sS[j] = acc;
            }
            __syncthreads();

            float v = 0.f, e = 0.f;
            if (tid < 256) {
                v = sS[tid];
                float m = wmax(v);
                if (lane == 0) sRed[wp] = m;
            }
            __syncthreads();
            if (tid < 256) {
                float m = sRed[0];
                #pragma unroll
                for (int i = 1; i < 8; i++) m = fmaxf(m, sRed[i]);
                e = expf(v - m);
                float s = wsum(e);
                if (lane == 0) sRedB[wp] = s;
            }
            __syncthreads();
            if (tid < 256) {
                float s = sRedB[0];
                #pragma unroll
                for (int i = 1; i < 8; i++) s += sRedB[i];
                sS[tid] = e / s;
            }
            __syncthreads();

            int p = tid & 255, q4i = tid >> 8;
            const __half2* kb = (const __half2*)g_keys16 + (size_t)b * S_ * (A_ / 2) + p;
            float2 acc2 = make_float2(0.f, 0.f);
            #pragma unroll 4
            for (int j0 = 0; j0 < 64; j0++) {
                int j = q4i * 64 + j0;
                float w = sS[j];
                float2 kv = __half22float2(kb[(size_t)j * (A_ / 2)]);
                acc2.x = fmaf(w, kv.x, acc2.x);
                acc2.y = fmaf(w, kv.y, acc2.y);
            }
            sCtx[q4i * 256 + p] = acc2;
            __syncthreads();
            if (tid < 256) {
                float2 a = sCtx[tid], b2 = sCtx[256 + tid], c2 = sCtx[512 + tid], d2 = sCtx[768 + tid];
                float2 sr = make_float2(a.x + b2.x + c2.x + d2.x, a.y + b2.y + c2.y + d2.y);
                ((__half2*)(g_Xh + (size_t)b * KX))[tid] = __float22half2_rn(sr);
            }
        }
        gridsync(sc);

        // ==== PC: gates slice n0 = bid*16, full K=1024, fused LSTM cell ====
        {
            const int n0 = bid * 16;
            const int mg = wp >> 3, kg = wp & 7;
            float cfr[2][2][4];
            #pragma unroll
            for (int i = 0; i < 2; i++)
                #pragma unroll
                for (int j = 0; j < 2; j++)
                    #pragma unroll
                    for (int q = 0; q < 4; q++) cfr[i][j][q] = 0.f;

            for (int kc = 0; kc < 8; kc++) {
                __syncthreads();
                #pragma unroll
                for (int r = 0; r < 2; r++) {
                    int idx = tid + r * 1024;
                    int row = idx >> 4, ch = idx & 15;
                    int chs = ch ^ (row & 7);
                    *(uint4*)(dyn + row * 256 + chs * 16) =
                        *(const uint4*)(g_Xh + (size_t)row * KX + kc * 128 + ch * 8);
                }
                if (tid < 256) {
                    int row = tid >> 4, ch = tid & 15;
                    int chs = ch ^ (row & 7);
                    *(uint4*)(dyn + SM_B_OFF + row * 256 + chs * 16) =
                        *(const uint4*)(g_Wcat16 + (size_t)(n0 + row) * KX + kc * 128 + ch * 8);
                }
                __syncthreads();
                uint32_t a0[4], a1[4], bb[4];
                int s = kg;
                int row = mg * 32 + (lane & 15);
                int ch = (s * 2 + (lane >> 4)) ^ (row & 7);
                ldmx4(a0, sb + row * 256 + ch * 16);
                row += 16; ch = (s * 2 + (lane >> 4)) ^ (row & 7);
                ldmx4(a1, sb + row * 256 + ch * 16);
                int n = ((lane >> 4) << 3) + (lane & 7);
                ch = (s * 2 + ((lane >> 3) & 1)) ^ (n & 7);
                ldmx4(bb, sb + SM_B_OFF + n * 256 + ch * 16);
                mma16816(cfr[0][0], a0, bb[0], bb[1]);
                mma16816(cfr[0][1], a0, bb[2], bb[3]);
                mma16816(cfr[1][0], a1, bb[0], bb[1]);
                mma16816(cfr[1][1], a1, bb[2], bb[3]);
            }
            // store k-group partials to smem
            float* buf = sRbuf + kg * (128 * 16);
            int g = lane >> 2, tt = lane & 3;
            #pragma unroll
            for (int mf = 0; mf < 2; mf++)
                #pragma unroll
                for (int nf = 0; nf < 2; nf++) {
                    int r0 = mg * 32 + mf * 16 + g;
                    int cc = nf * 8 + 2 * tt;
                    float* c = cfr[mf][nf];
                    *(float2*)(buf + r0 * 16 + cc) = make_float2(c[0], c[1]);
                    *(float2*)(buf + (r0 + 8) * 16 + cc) = make_float2(c[2], c[3]);
                }
            __syncthreads();
            // fused cell: 512 threads, one (b, j) each
            if (tid < 512) {
                int b = tid >> 2, jl = tid & 3;
                float4 s0 = make_float4(0.f, 0.f, 0.f, 0.f);
                #pragma unroll
                for (int kg2 = 0; kg2 < 8; kg2++) {
                    float4 v4 = *(const float4*)(sRbuf + kg2 * 2048 + b * 16 + jl * 4);
                    s0.x += v4.x; s0.y += v4.y; s0.z += v4.z; s0.w += v4.w;
                }
                int n = n0 + jl * 4;
                int lbl = labels[b * T_ + (t > 0 ? t - 1 : 0)];
                float4 bc = *(const float4*)(g_bcombIl + n);
                float4 wv = *(const float4*)(g_WihVTil + (size_t)lbl * NG + n);
                s0.x += bc.x + wv.x; s0.y += bc.y + wv.y;
                s0.z += bc.z + wv.z; s0.w += bc.w + wv.w;
                int j = bid * 4 + jl;
                float c = g_c[b * H_ + j];
                float cn = sigm(s0.y) * c + sigm(s0.x) * tanhf(s0.z);
                float hn = sigm(s0.w) * tanhf(cn);
                g_c[b * H_ + j] = cn;
                __half hh = __float2half(hn);
                g_h16[b * H_ + j] = hh;
                g_Xh[(size_t)b * KX + A_ + j] = hh;
            }
        }
        gridsync(sc);
    }

    // final out row t = T-1
    if (bid >= 64 && bid < 96) {
        int n0 = (bid - 64) * 8;
        mma_gemm_n8(g_h16, H_, g_Wout16, H_, n0, H_, dyn, sb);
        int b = tid >> 3, nl = tid & 7;
        float s = bout[n0 + nl];
        #pragma unroll
        for (int kg = 0; kg < 8; kg++) s += sRbuf[kg * 1024 + b * 8 + nl];
        out[((size_t)b * T_ + (T_ - 1)) * V_ + n0 + nl] = s;
    }
}

// ---------------- host driver ----------------
extern "C" void kernel_launch(void* const* d_in, const int* in_sizes, int n_in,
                              void* d_out, int out_size) {
    (void)in_sizes; (void)n_in; (void)out_size;
    const float* feats = (const float*)d_in[0];
    const int*   labels= (const int*)  d_in[1];
    const float* Ic_w  = (const float*)d_in[2];
    const float* Ic_b  = (const float*)d_in[3];
    const float* Hc_w  = (const float*)d_in[4];
    const float* Hc_b  = (const float*)d_in[5];
    const float* Wq    = (const float*)d_in[6];
    const float* bq    = (const float*)d_in[7];
    const float* Wk    = (const float*)d_in[8];
    const float* bk    = (const float*)d_in[9];
    const float* va    = (const float*)d_in[10];
    const float* W_ih  = (const float*)d_in[11];
    const float* b_ih  = (const float*)d_in[12];
    const float* W_hh  = (const float*)d_in[13];
    const float* b_hh  = (const float*)d_in[14];
    const float* Wout  = (const float*)d_in[15];
    const float* bout  = (const float*)d_in[16];
    float* out = (float*)d_out;

    __half *p_feats16, *p_keys16, *p_kproj16, *p_Icw16, *p_Wk16, *p_Wcomb16, *p_Wout16;
    float *p_HcT;
    cudaGetSymbolAddress((void**)&p_feats16, g_feats16);
    cudaGetSymbolAddress((void**)&p_keys16,  g_keys16);
    cudaGetSymbolAddress((void**)&p_kproj16, g_kproj16);
    cudaGetSymbolAddress((void**)&p_Icw16,   g_Icw16);
    cudaGetSymbolAddress((void**)&p_Wk16,    g_Wk16);
    cudaGetSymbolAddress((void**)&p_Wcomb16, g_Wcomb16);
    cudaGetSymbolAddress((void**)&p_Wout16,  g_Wout16);
    cudaGetSymbolAddress((void**)&p_HcT,     g_HcT);

    static bool attr_done = false;
    if (!attr_done) {
        cudaFuncSetAttribute(persist, cudaFuncAttributeMaxDynamicSharedMemorySize, SMEM_DYN);
        attr_done = true;
    }

    // conversions
    k_cvt<<<(B_*S_*C_ + 255)/256, 256>>>(feats, p_feats16, B_*S_*C_);
    k_cvt<<<(A_*C_ + 255)/256, 256>>>(Ic_w, p_Icw16, A_*C_);
    k_cvt<<<(A_*A_ + 255)/256, 256>>>(Wk, p_Wk16, A_*A_);
    k_cvt<<<(V_*H_ + 255)/256, 256>>>(Wout, p_Wout16, V_*H_);

    // small precompute
    k_transpose<<<(A_*H_ + 255)/256, 256>>>(Hc_w, p_HcT, A_, H_);
    gemm_wcomb<<<dim3(H_/64, A_/64), 256>>>(Wq, p_HcT, p_Wcomb16, A_, H_, A_);
    k_bqc<<<1, 512>>>(Wq, bq, Hc_b);
    k_wcat_il<<<(NG*KX)/256, 256>>>(W_ih, W_hh, b_ih, b_hh);
    k_wihvt<<<(V_*NG)/256, 256>>>(W_ih);
    k_zero<<<(B_*H_)/256, 256>>>();

    // keys16 = feats @ Ic_w^T + Ic_b ; kproj16 = keys16 @ Wk^T + bk
    mma_pre<<<dim3(A_/64, (B_*S_)/64), 256>>>(p_feats16, p_Icw16, Ic_b, p_keys16,  C_, A_);
    mma_pre<<<dim3(A_/64, (B_*S_)/64), 256>>>(p_keys16,  p_Wk16,  bk,   p_kproj16, A_, A_);

    // persistent decode
    persist<<<NBLK, 1024, SMEM_DYN>>>(labels, va, bout, out);
}